// round 1
// baseline (speedup 1.0000x reference)
#include <cuda_runtime.h>
#include <cuda_bf16.h>
#include <math.h>

// Problem constants
#define S_LEN   3072
#define HIDDEN  2048
#define HQ      16
#define HK      2
#define HEADDIM 128
#define KVDIM   (HK * HEADDIM)   // 256

// ---------------------------------------------------------------------------
// Scratch (static device globals; no allocation allowed)
// ---------------------------------------------------------------------------
__device__ float g_Q[S_LEN * HIDDEN];      // [S, 16*128]
__device__ float g_K[S_LEN * KVDIM];       // [S, 2*128]
__device__ float g_V[S_LEN * KVDIM];
__device__ float g_attn[S_LEN * HIDDEN];   // attention output, pre-Wo
__device__ float g_cos[S_LEN * 64];
__device__ float g_sin[S_LEN * 64];

// ---------------------------------------------------------------------------
// RoPE tables: fp32 inv_freq (shared rounding with the fp32 reference),
// fp64 angle/trig to avoid fp32 argument-reduction divergence at pos~3071.
// ---------------------------------------------------------------------------
__global__ void rope_tables_kernel(const int* __restrict__ pos_ids) {
    int s = blockIdx.x;
    int i = threadIdx.x;  // 0..63
    int pos = pos_ids[s];
    float invf = 1.0f / powf(10000.0f, (float)(2 * i) / 128.0f);
    double ang = (double)pos * (double)invf;
    double sv, cv;
    sincos(ang, &sv, &cv);
    g_cos[s * 64 + i] = (float)cv;
    g_sin[s * 64 + i] = (float)sv;
}

// Apply RoPE in place to Q (heads 0..15) and K (heads 16..17).
__global__ void rope_apply_kernel() {
    int s = blockIdx.x;
    int h = blockIdx.y;   // 0..17
    int i = threadIdx.x;  // 0..63
    float c  = g_cos[s * 64 + i];
    float sn = g_sin[s * 64 + i];
    float* base;
    if (h < HQ) base = g_Q + (size_t)s * HIDDEN + (size_t)h * HEADDIM;
    else        base = g_K + (size_t)s * KVDIM  + (size_t)(h - HQ) * HEADDIM;
    float x1 = base[i];
    float x2 = base[i + 64];
    base[i]      = x1 * c - x2 * sn;
    base[i + 64] = x2 * c + x1 * sn;
}

// ---------------------------------------------------------------------------
// fp32 GEMM: C[M,N] = A[M,K] * B[N,K]^T  (both row-major, K contiguous)
// BM=BN=128, BK=16, 256 threads, 8x8 micro-tile.
// ---------------------------------------------------------------------------
__global__ void __launch_bounds__(256) sgemm_nt_kernel(
    const float* __restrict__ A, const float* __restrict__ B,
    float* __restrict__ C, int M, int N, int K)
{
    __shared__ float As[16][132];  // [k][m], padded stride (2-way store conflict max)
    __shared__ float Bs[16][132];  // [k][n]

    const int bm = blockIdx.y * 128;
    const int bn = blockIdx.x * 128;
    const int tid = threadIdx.x;
    const int tr = tid >> 4;   // 0..15
    const int tc = tid & 15;   // 0..15

    float acc[8][8];
#pragma unroll
    for (int r = 0; r < 8; r++)
#pragma unroll
        for (int c = 0; c < 8; c++) acc[r][c] = 0.0f;

    for (int k0 = 0; k0 < K; k0 += 16) {
#pragma unroll
        for (int t = 0; t < 2; t++) {
            int i = tid + t * 256;       // 0..511 float4 slots
            int row = i >> 2;            // 0..127
            int kg  = (i & 3) << 2;      // 0,4,8,12
            float4 va = *(const float4*)&A[(size_t)(bm + row) * K + k0 + kg];
            As[kg + 0][row] = va.x; As[kg + 1][row] = va.y;
            As[kg + 2][row] = va.z; As[kg + 3][row] = va.w;
            float4 vb = *(const float4*)&B[(size_t)(bn + row) * K + k0 + kg];
            Bs[kg + 0][row] = vb.x; Bs[kg + 1][row] = vb.y;
            Bs[kg + 2][row] = vb.z; Bs[kg + 3][row] = vb.w;
        }
        __syncthreads();
#pragma unroll
        for (int kk = 0; kk < 16; kk++) {
            float4 a0 = *(const float4*)&As[kk][tr * 8];
            float4 a1 = *(const float4*)&As[kk][tr * 8 + 4];
            float4 b0 = *(const float4*)&Bs[kk][tc * 8];
            float4 b1 = *(const float4*)&Bs[kk][tc * 8 + 4];
            float a[8] = {a0.x, a0.y, a0.z, a0.w, a1.x, a1.y, a1.z, a1.w};
            float b[8] = {b0.x, b0.y, b0.z, b0.w, b1.x, b1.y, b1.z, b1.w};
#pragma unroll
            for (int r = 0; r < 8; r++)
#pragma unroll
                for (int c = 0; c < 8; c++) acc[r][c] += a[r] * b[c];
        }
        __syncthreads();
    }

#pragma unroll
    for (int r = 0; r < 8; r++) {
        size_t off = (size_t)(bm + tr * 8 + r) * N + bn + tc * 8;
        float4 o0 = make_float4(acc[r][0], acc[r][1], acc[r][2], acc[r][3]);
        float4 o1 = make_float4(acc[r][4], acc[r][5], acc[r][6], acc[r][7]);
        *(float4*)&C[off]     = o0;
        *(float4*)&C[off + 4] = o1;
    }
}

// ---------------------------------------------------------------------------
// Flash attention (fp32, causal). Grid: (48 q-tiles, 16 heads), 256 threads.
// BM=BN=64, D=128. Online softmax; P staged through smem for the O-GEMM.
// smem: Qs 32KB + Kst 32KB (transposed) + Vs 32KB + Ps 16KB = 112KB.
// ---------------------------------------------------------------------------
__global__ void __launch_bounds__(256) flash_attn_kernel() {
    extern __shared__ float sm[];
    float* Qs  = sm;            // [64][128]
    float* Kst = sm + 8192;     // [128][64]  (d-major, conflict-free col reads)
    float* Vs  = sm + 16384;    // [64][128]
    float* Ps  = sm + 24576;    // [64][64]

    const int qt = blockIdx.x;        // query tile
    const int h  = blockIdx.y;        // head
    const int kvh = h & (HK - 1);     // GQA: kv head = h % 2
    const int tid = threadIdx.x;
    const int tr = tid >> 4;          // 0..15  (owns query rows tr*4..+3)
    const int tc = tid & 15;          // 0..15  (owns score cols tc*4..+3, d cols tc*8..+7)

    const float* Qg = g_Q + (size_t)qt * 64 * HIDDEN + (size_t)h * HEADDIM;
#pragma unroll
    for (int t = 0; t < 8; t++) {
        int i = tid + t * 256;        // 0..2047 float4 slots
        int row = i >> 5, c4 = (i & 31) << 2;
        *(float4*)&Qs[row * 128 + c4] = *(const float4*)&Qg[(size_t)row * HIDDEN + c4];
    }

    float m[4], l[4], o[4][8];
#pragma unroll
    for (int r = 0; r < 4; r++) {
        m[r] = -INFINITY; l[r] = 0.0f;
#pragma unroll
        for (int d = 0; d < 8; d++) o[r][d] = 0.0f;
    }
    const float scale = 0.08838834764831845f;  // 1/sqrt(128)

    for (int kt = 0; kt <= qt; kt++) {
        const float* Kg = g_K + (size_t)kt * 64 * KVDIM + (size_t)kvh * HEADDIM;
        const float* Vg = g_V + (size_t)kt * 64 * KVDIM + (size_t)kvh * HEADDIM;
#pragma unroll
        for (int t = 0; t < 8; t++) {
            int i = tid + t * 256;
            {   // K transposed: lane==row -> conflict-free smem stores
                int row = i & 63, cg = i >> 6;          // cg 0..31
                float4 kv = *(const float4*)&Kg[(size_t)row * KVDIM + (cg << 2)];
                Kst[((cg << 2) + 0) * 64 + row] = kv.x;
                Kst[((cg << 2) + 1) * 64 + row] = kv.y;
                Kst[((cg << 2) + 2) * 64 + row] = kv.z;
                Kst[((cg << 2) + 3) * 64 + row] = kv.w;
            }
            {   // V row-major, coalesced
                int row = i >> 5, c4 = (i & 31) << 2;
                *(float4*)&Vs[row * 128 + c4] = *(const float4*)&Vg[(size_t)row * KVDIM + c4];
            }
        }
        __syncthreads();

        // S = Q * K^T  (4x4 per thread)
        float s[4][4];
#pragma unroll
        for (int r = 0; r < 4; r++)
#pragma unroll
            for (int c = 0; c < 4; c++) s[r][c] = 0.0f;

#pragma unroll 4
        for (int d4 = 0; d4 < 32; d4++) {
            float4 qv[4], kv[4];
#pragma unroll
            for (int r = 0; r < 4; r++)
                qv[r] = *(const float4*)&Qs[(tr * 4 + r) * 128 + (d4 << 2)];
#pragma unroll
            for (int u = 0; u < 4; u++)
                kv[u] = *(const float4*)&Kst[((d4 << 2) + u) * 64 + (tc << 2)];
#pragma unroll
            for (int r = 0; r < 4; r++) {
                s[r][0] += qv[r].x * kv[0].x; s[r][1] += qv[r].x * kv[0].y;
                s[r][2] += qv[r].x * kv[0].z; s[r][3] += qv[r].x * kv[0].w;
                s[r][0] += qv[r].y * kv[1].x; s[r][1] += qv[r].y * kv[1].y;
                s[r][2] += qv[r].y * kv[1].z; s[r][3] += qv[r].y * kv[1].w;
                s[r][0] += qv[r].z * kv[2].x; s[r][1] += qv[r].z * kv[2].y;
                s[r][2] += qv[r].z * kv[2].z; s[r][3] += qv[r].z * kv[2].w;
                s[r][0] += qv[r].w * kv[3].x; s[r][1] += qv[r].w * kv[3].y;
                s[r][2] += qv[r].w * kv[3].z; s[r][3] += qv[r].w * kv[3].w;
            }
        }

        // scale + causal mask on the diagonal tile
#pragma unroll
        for (int r = 0; r < 4; r++)
#pragma unroll
            for (int c = 0; c < 4; c++) s[r][c] *= scale;
        if (kt == qt) {
#pragma unroll
            for (int r = 0; r < 4; r++)
#pragma unroll
                for (int c = 0; c < 4; c++)
                    if (tc * 4 + c > tr * 4 + r) s[r][c] = -INFINITY;
        }

        // online softmax (row stats across the 16 lanes sharing tr)
#pragma unroll
        for (int r = 0; r < 4; r++) {
            float rowm = fmaxf(fmaxf(s[r][0], s[r][1]), fmaxf(s[r][2], s[r][3]));
#pragma unroll
            for (int off = 8; off > 0; off >>= 1)
                rowm = fmaxf(rowm, __shfl_xor_sync(0xffffffffu, rowm, off, 16));
            float mnew = fmaxf(m[r], rowm);
            float alpha = expf(m[r] - mnew);
            m[r] = mnew;
            float rs = 0.0f;
#pragma unroll
            for (int c = 0; c < 4; c++) {
                float p = expf(s[r][c] - mnew);
                s[r][c] = p;
                rs += p;
            }
#pragma unroll
            for (int off = 8; off > 0; off >>= 1)
                rs += __shfl_xor_sync(0xffffffffu, rs, off, 16);
            l[r] = l[r] * alpha + rs;
#pragma unroll
            for (int d = 0; d < 8; d++) o[r][d] *= alpha;
            *(float4*)&Ps[(tr * 4 + r) * 64 + (tc << 2)] =
                make_float4(s[r][0], s[r][1], s[r][2], s[r][3]);
        }
        __syncthreads();

        // O += P * V   (4 rows x 8 d-cols per thread)
#pragma unroll 4
        for (int j = 0; j < 64; j++) {
            float4 v0 = *(const float4*)&Vs[j * 128 + (tc << 3)];
            float4 v1 = *(const float4*)&Vs[j * 128 + (tc << 3) + 4];
#pragma unroll
            for (int r = 0; r < 4; r++) {
                float p = Ps[(tr * 4 + r) * 64 + j];
                o[r][0] += p * v0.x; o[r][1] += p * v0.y;
                o[r][2] += p * v0.z; o[r][3] += p * v0.w;
                o[r][4] += p * v1.x; o[r][5] += p * v1.y;
                o[r][6] += p * v1.z; o[r][7] += p * v1.w;
            }
        }
        __syncthreads();
    }

    float* Og = g_attn + (size_t)qt * 64 * HIDDEN + (size_t)h * HEADDIM;
#pragma unroll
    for (int r = 0; r < 4; r++) {
        float inv = 1.0f / l[r];
        size_t off = (size_t)(tr * 4 + r) * HIDDEN + (tc << 3);
        *(float4*)&Og[off] = make_float4(o[r][0] * inv, o[r][1] * inv,
                                         o[r][2] * inv, o[r][3] * inv);
        *(float4*)&Og[off + 4] = make_float4(o[r][4] * inv, o[r][5] * inv,
                                             o[r][6] * inv, o[r][7] * inv);
    }
}

// ---------------------------------------------------------------------------
// Launch
// ---------------------------------------------------------------------------
extern "C" void kernel_launch(void* const* d_in, const int* in_sizes, int n_in,
                              void* d_out, int out_size) {
    const float* x   = (const float*)d_in[0];   // hidden_states [1,3072,2048]
    // d_in[1]: attention_mask (causal triu, known statically; unused)
    const int*   pos = (const int*)d_in[2];     // position_ids [1,3072] int32
    const float* Wq  = (const float*)d_in[3];   // [2048,2048]
    const float* Wk  = (const float*)d_in[4];   // [256,2048]
    const float* Wv  = (const float*)d_in[5];   // [256,2048]
    const float* Wo  = (const float*)d_in[6];   // [2048,2048]
    float* out = (float*)d_out;                 // [1,3072,2048] fp32

    float *q, *k, *v, *attn;
    cudaGetSymbolAddress((void**)&q,    g_Q);
    cudaGetSymbolAddress((void**)&k,    g_K);
    cudaGetSymbolAddress((void**)&v,    g_V);
    cudaGetSymbolAddress((void**)&attn, g_attn);

    // Projections
    sgemm_nt_kernel<<<dim3(HIDDEN / 128, S_LEN / 128), 256>>>(x, Wq, q, S_LEN, HIDDEN, HIDDEN);
    sgemm_nt_kernel<<<dim3(KVDIM / 128,  S_LEN / 128), 256>>>(x, Wk, k, S_LEN, KVDIM, HIDDEN);
    sgemm_nt_kernel<<<dim3(KVDIM / 128,  S_LEN / 128), 256>>>(x, Wv, v, S_LEN, KVDIM, HIDDEN);

    // RoPE
    rope_tables_kernel<<<S_LEN, 64>>>(pos);
    rope_apply_kernel<<<dim3(S_LEN, HQ + HK), 64>>>();

    // Flash attention
    cudaFuncSetAttribute(flash_attn_kernel,
                         cudaFuncAttributeMaxDynamicSharedMemorySize, 114688);
    flash_attn_kernel<<<dim3(S_LEN / 64, HQ), 256, 114688>>>();

    // Output projection
    sgemm_nt_kernel<<<dim3(HIDDEN / 128, S_LEN / 128), 256>>>(attn, Wo, out, S_LEN, HIDDEN, HIDDEN);
}

// round 2
// speedup vs baseline: 1.2678x; 1.2678x over previous
#include <cuda_runtime.h>
#include <cuda_bf16.h>
#include <math.h>

// Problem constants
#define S_LEN   3072
#define HIDDEN  2048
#define HQ      16
#define HK      2
#define HEADDIM 128
#define KVDIM   (HK * HEADDIM)   // 256

// ---------------------------------------------------------------------------
// Scratch (static device globals; no allocation allowed)
// ---------------------------------------------------------------------------
__device__ float g_Q[S_LEN * HIDDEN];      // [S, 16*128]
__device__ float g_K[S_LEN * KVDIM];       // [S, 2*128]
__device__ float g_V[S_LEN * KVDIM];
__device__ float g_attn[S_LEN * HIDDEN];   // attention output, pre-Wo
__device__ float g_cos[S_LEN * 64];
__device__ float g_sin[S_LEN * 64];

// ---------------------------------------------------------------------------
// RoPE tables: fp32 inv_freq (shared rounding with the fp32 reference),
// fp64 angle/trig to avoid fp32 argument-reduction divergence at pos~3071.
// ---------------------------------------------------------------------------
__global__ void rope_tables_kernel(const int* __restrict__ pos_ids) {
    int s = blockIdx.x;
    int i = threadIdx.x;  // 0..63
    int pos = pos_ids[s];
    float invf = 1.0f / powf(10000.0f, (float)(2 * i) / 128.0f);
    double ang = (double)pos * (double)invf;
    double sv, cv;
    sincos(ang, &sv, &cv);
    g_cos[s * 64 + i] = (float)cv;
    g_sin[s * 64 + i] = (float)sv;
}

// Apply RoPE in place to Q (heads 0..15) and K (heads 16..17).
__global__ void rope_apply_kernel() {
    int s = blockIdx.x;
    int h = blockIdx.y;   // 0..17
    int i = threadIdx.x;  // 0..63
    float c  = g_cos[s * 64 + i];
    float sn = g_sin[s * 64 + i];
    float* base;
    if (h < HQ) base = g_Q + (size_t)s * HIDDEN + (size_t)h * HEADDIM;
    else        base = g_K + (size_t)s * KVDIM  + (size_t)(h - HQ) * HEADDIM;
    float x1 = base[i];
    float x2 = base[i + 64];
    base[i]      = x1 * c - x2 * sn;
    base[i + 64] = x2 * c + x1 * sn;
}

// ---------------------------------------------------------------------------
// TF32 tensor-core GEMM: C[M,N] = A[M,K] * B[N,K]^T (row-major, K contiguous)
// BM=BN=128, BK=32. 256 threads = 8 warps (2x4), 64x32 per warp.
// Smem tiles stored fragment-permuted so fragment reads are single LDS.128/64.
// Double-buffered smem (64KB dynamic) + register-staged global prefetch.
// ---------------------------------------------------------------------------
__device__ __forceinline__ unsigned f2tf32(float f) {
    unsigned r;
    asm("cvt.rna.tf32.f32 %0, %1;" : "=r"(r) : "f"(f));
    return r;
}

#define MMA_TF32(d, a, b)                                                     \
    asm volatile(                                                             \
        "mma.sync.aligned.m16n8k8.row.col.f32.tf32.tf32.f32 "                 \
        "{%0,%1,%2,%3},{%4,%5,%6,%7},{%8,%9},{%0,%1,%2,%3};"                  \
        : "+f"(d[0]), "+f"(d[1]), "+f"(d[2]), "+f"(d[3])                      \
        : "r"(a.x), "r"(a.y), "r"(a.z), "r"(a.w), "r"(b.x), "r"(b.y))

// Smem sizes (floats) per buffer
#define AS_FLOATS 4096   // 8 mtiles * 4 ksteps * 32 lanes * 4 regs
#define BS_FLOATS 4096   // 16 ntiles * 4 ksteps * 32 lanes * 2 regs

__global__ void __launch_bounds__(256) gemm_tf32_nt(
    const float* __restrict__ A, const float* __restrict__ B,
    float* __restrict__ C, int M, int N, int K)
{
    extern __shared__ float sm[];
    float* Asm[2] = { sm,                       sm + AS_FLOATS };
    float* Bsm[2] = { sm + 2 * AS_FLOATS,       sm + 2 * AS_FLOATS + BS_FLOATS };

    const int tid  = threadIdx.x;
    const int lane = tid & 31;
    const int wid  = tid >> 5;
    const int warp_m = wid >> 2;   // 0..1
    const int warp_n = wid & 3;    // 0..3
    const int bm = blockIdx.y * 128;
    const int bn = blockIdx.x * 128;

    const float* Ab = A + (size_t)bm * K;
    const float* Bb = B + (size_t)bn * K;

    float acc[16][4];
#pragma unroll
    for (int i = 0; i < 16; i++)
#pragma unroll
        for (int j = 0; j < 4; j++) acc[i][j] = 0.0f;

    const int T = K >> 5;  // K/32 tiles

    // --- tile loader: global float4 -> fragment-permuted smem (tf32) ---
    auto store_tile = [&](float* As, float* Bs, const float4* ra, const float4* rb) {
#pragma unroll
        for (int j = 0; j < 4; j++) {
            int i = tid + j * 256;        // 0..1023
            int row = i >> 3;             // 0..127
            int kg  = (i & 7) << 2;       // 0,4,..,28
            int mtile = row >> 4, kstep = kg >> 3;
            int lane_s = (row & 7) << 2;
            int reg = ((row >> 3) & 1) | (((kg >> 2) & 1) << 1);
            float* pa = As + ((mtile * 4 + kstep) << 7) + reg;
            pa[(lane_s + 0) * 4] = __uint_as_float(f2tf32(ra[j].x));
            pa[(lane_s + 1) * 4] = __uint_as_float(f2tf32(ra[j].y));
            pa[(lane_s + 2) * 4] = __uint_as_float(f2tf32(ra[j].z));
            pa[(lane_s + 3) * 4] = __uint_as_float(f2tf32(ra[j].w));

            int n = row;                  // same index pattern for B
            int ntile = n >> 3;
            int lane_b = (n & 7) << 2;
            int regb = (kg >> 2) & 1;
            float* pb = Bs + ((ntile * 4 + kstep) << 6) + regb;
            pb[(lane_b + 0) * 2] = __uint_as_float(f2tf32(rb[j].x));
            pb[(lane_b + 1) * 2] = __uint_as_float(f2tf32(rb[j].y));
            pb[(lane_b + 2) * 2] = __uint_as_float(f2tf32(rb[j].z));
            pb[(lane_b + 3) * 2] = __uint_as_float(f2tf32(rb[j].w));
        }
    };
    auto load_regs = [&](int t, float4* ra, float4* rb) {
        int k0 = t << 5;
#pragma unroll
        for (int j = 0; j < 4; j++) {
            int i = tid + j * 256;
            int row = i >> 3;
            int kg  = (i & 7) << 2;
            ra[j] = *(const float4*)&Ab[(size_t)row * K + k0 + kg];
            rb[j] = *(const float4*)&Bb[(size_t)row * K + k0 + kg];
        }
    };

    {   // prologue: tile 0
        float4 ra[4], rb[4];
        load_regs(0, ra, rb);
        store_tile(Asm[0], Bsm[0], ra, rb);
    }
    __syncthreads();

    for (int t = 0; t < T; t++) {
        const int buf = t & 1;
        float4 ra[4], rb[4];
        if (t + 1 < T) load_regs(t + 1, ra, rb);

        const float* As = Asm[buf];
        const float* Bs = Bsm[buf];
#pragma unroll
        for (int kstep = 0; kstep < 4; kstep++) {
            uint4 af[4];
            uint2 bf[4];
#pragma unroll
            for (int mi = 0; mi < 4; mi++)
                af[mi] = *(const uint4*)&As[(((warp_m * 4 + mi) * 4 + kstep) << 7) + lane * 4];
#pragma unroll
            for (int ni = 0; ni < 4; ni++)
                bf[ni] = *(const uint2*)&Bs[(((warp_n * 4 + ni) * 4 + kstep) << 6) + lane * 2];
#pragma unroll
            for (int mi = 0; mi < 4; mi++)
#pragma unroll
                for (int ni = 0; ni < 4; ni++)
                    MMA_TF32(acc[mi * 4 + ni], af[mi], bf[ni]);
        }

        if (t + 1 < T) store_tile(Asm[1 - buf], Bsm[1 - buf], ra, rb);
        __syncthreads();
    }

    // epilogue
#pragma unroll
    for (int mi = 0; mi < 4; mi++) {
#pragma unroll
        for (int ni = 0; ni < 4; ni++) {
            const float* d = acc[mi * 4 + ni];
            int r0 = bm + warp_m * 64 + mi * 16 + (lane >> 2);
            int c0 = bn + warp_n * 32 + ni * 8 + (lane & 3) * 2;
            *(float2*)&C[(size_t)r0 * N + c0]       = make_float2(d[0], d[1]);
            *(float2*)&C[(size_t)(r0 + 8) * N + c0] = make_float2(d[2], d[3]);
        }
    }
}

// ---------------------------------------------------------------------------
// Flash attention (fp32, causal). Grid: (48 q-tiles, 16 heads), 256 threads.
// ---------------------------------------------------------------------------
__global__ void __launch_bounds__(256) flash_attn_kernel() {
    extern __shared__ float smf[];
    float* Qs  = smf;           // [64][128]
    float* Kst = smf + 8192;    // [128][64]  (d-major)
    float* Vs  = smf + 16384;   // [64][128]
    float* Ps  = smf + 24576;   // [64][64]

    const int qt = blockIdx.x;
    const int h  = blockIdx.y;
    const int kvh = h & (HK - 1);
    const int tid = threadIdx.x;
    const int tr = tid >> 4;
    const int tc = tid & 15;

    const float* Qg = g_Q + (size_t)qt * 64 * HIDDEN + (size_t)h * HEADDIM;
#pragma unroll
    for (int t = 0; t < 8; t++) {
        int i = tid + t * 256;
        int row = i >> 5, c4 = (i & 31) << 2;
        *(float4*)&Qs[row * 128 + c4] = *(const float4*)&Qg[(size_t)row * HIDDEN + c4];
    }

    float m[4], l[4], o[4][8];
#pragma unroll
    for (int r = 0; r < 4; r++) {
        m[r] = -INFINITY; l[r] = 0.0f;
#pragma unroll
        for (int d = 0; d < 8; d++) o[r][d] = 0.0f;
    }
    const float scale = 0.08838834764831845f;

    for (int kt = 0; kt <= qt; kt++) {
        const float* Kg = g_K + (size_t)kt * 64 * KVDIM + (size_t)kvh * HEADDIM;
        const float* Vg = g_V + (size_t)kt * 64 * KVDIM + (size_t)kvh * HEADDIM;
#pragma unroll
        for (int t = 0; t < 8; t++) {
            int i = tid + t * 256;
            {
                int row = i & 63, cg = i >> 6;
                float4 kv = *(const float4*)&Kg[(size_t)row * KVDIM + (cg << 2)];
                Kst[((cg << 2) + 0) * 64 + row] = kv.x;
                Kst[((cg << 2) + 1) * 64 + row] = kv.y;
                Kst[((cg << 2) + 2) * 64 + row] = kv.z;
                Kst[((cg << 2) + 3) * 64 + row] = kv.w;
            }
            {
                int row = i >> 5, c4 = (i & 31) << 2;
                *(float4*)&Vs[row * 128 + c4] = *(const float4*)&Vg[(size_t)row * KVDIM + c4];
            }
        }
        __syncthreads();

        float s[4][4];
#pragma unroll
        for (int r = 0; r < 4; r++)
#pragma unroll
            for (int c = 0; c < 4; c++) s[r][c] = 0.0f;

#pragma unroll 4
        for (int d4 = 0; d4 < 32; d4++) {
            float4 qv[4], kv[4];
#pragma unroll
            for (int r = 0; r < 4; r++)
                qv[r] = *(const float4*)&Qs[(tr * 4 + r) * 128 + (d4 << 2)];
#pragma unroll
            for (int u = 0; u < 4; u++)
                kv[u] = *(const float4*)&Kst[((d4 << 2) + u) * 64 + (tc << 2)];
#pragma unroll
            for (int r = 0; r < 4; r++) {
                s[r][0] += qv[r].x * kv[0].x; s[r][1] += qv[r].x * kv[0].y;
                s[r][2] += qv[r].x * kv[0].z; s[r][3] += qv[r].x * kv[0].w;
                s[r][0] += qv[r].y * kv[1].x; s[r][1] += qv[r].y * kv[1].y;
                s[r][2] += qv[r].y * kv[1].z; s[r][3] += qv[r].y * kv[1].w;
                s[r][0] += qv[r].z * kv[2].x; s[r][1] += qv[r].z * kv[2].y;
                s[r][2] += qv[r].z * kv[2].z; s[r][3] += qv[r].z * kv[2].w;
                s[r][0] += qv[r].w * kv[3].x; s[r][1] += qv[r].w * kv[3].y;
                s[r][2] += qv[r].w * kv[3].z; s[r][3] += qv[r].w * kv[3].w;
            }
        }

#pragma unroll
        for (int r = 0; r < 4; r++)
#pragma unroll
            for (int c = 0; c < 4; c++) s[r][c] *= scale;
        if (kt == qt) {
#pragma unroll
            for (int r = 0; r < 4; r++)
#pragma unroll
                for (int c = 0; c < 4; c++)
                    if (tc * 4 + c > tr * 4 + r) s[r][c] = -INFINITY;
        }

#pragma unroll
        for (int r = 0; r < 4; r++) {
            float rowm = fmaxf(fmaxf(s[r][0], s[r][1]), fmaxf(s[r][2], s[r][3]));
#pragma unroll
            for (int off = 8; off > 0; off >>= 1)
                rowm = fmaxf(rowm, __shfl_xor_sync(0xffffffffu, rowm, off, 16));
            float mnew = fmaxf(m[r], rowm);
            float alpha = expf(m[r] - mnew);
            m[r] = mnew;
            float rs = 0.0f;
#pragma unroll
            for (int c = 0; c < 4; c++) {
                float p = expf(s[r][c] - mnew);
                s[r][c] = p;
                rs += p;
            }
#pragma unroll
            for (int off = 8; off > 0; off >>= 1)
                rs += __shfl_xor_sync(0xffffffffu, rs, off, 16);
            l[r] = l[r] * alpha + rs;
#pragma unroll
            for (int d = 0; d < 8; d++) o[r][d] *= alpha;
            *(float4*)&Ps[(tr * 4 + r) * 64 + (tc << 2)] =
                make_float4(s[r][0], s[r][1], s[r][2], s[r][3]);
        }
        __syncthreads();

#pragma unroll 4
        for (int j = 0; j < 64; j++) {
            float4 v0 = *(const float4*)&Vs[j * 128 + (tc << 3)];
            float4 v1 = *(const float4*)&Vs[j * 128 + (tc << 3) + 4];
#pragma unroll
            for (int r = 0; r < 4; r++) {
                float p = Ps[(tr * 4 + r) * 64 + j];
                o[r][0] += p * v0.x; o[r][1] += p * v0.y;
                o[r][2] += p * v0.z; o[r][3] += p * v0.w;
                o[r][4] += p * v1.x; o[r][5] += p * v1.y;
                o[r][6] += p * v1.z; o[r][7] += p * v1.w;
            }
        }
        __syncthreads();
    }

    float* Og = g_attn + (size_t)qt * 64 * HIDDEN + (size_t)h * HEADDIM;
#pragma unroll
    for (int r = 0; r < 4; r++) {
        float inv = 1.0f / l[r];
        size_t off = (size_t)(tr * 4 + r) * HIDDEN + (tc << 3);
        *(float4*)&Og[off] = make_float4(o[r][0] * inv, o[r][1] * inv,
                                         o[r][2] * inv, o[r][3] * inv);
        *(float4*)&Og[off + 4] = make_float4(o[r][4] * inv, o[r][5] * inv,
                                             o[r][6] * inv, o[r][7] * inv);
    }
}

// ---------------------------------------------------------------------------
// Launch
// ---------------------------------------------------------------------------
extern "C" void kernel_launch(void* const* d_in, const int* in_sizes, int n_in,
                              void* d_out, int out_size) {
    const float* x   = (const float*)d_in[0];   // hidden_states [1,3072,2048]
    const int*   pos = (const int*)d_in[2];     // position_ids [1,3072] int32
    const float* Wq  = (const float*)d_in[3];   // [2048,2048]
    const float* Wk  = (const float*)d_in[4];   // [256,2048]
    const float* Wv  = (const float*)d_in[5];   // [256,2048]
    const float* Wo  = (const float*)d_in[6];   // [2048,2048]
    float* out = (float*)d_out;                 // [1,3072,2048] fp32

    float *q, *k, *v, *attn;
    cudaGetSymbolAddress((void**)&q,    g_Q);
    cudaGetSymbolAddress((void**)&k,    g_K);
    cudaGetSymbolAddress((void**)&v,    g_V);
    cudaGetSymbolAddress((void**)&attn, g_attn);

    const int GEMM_SMEM = 2 * (AS_FLOATS + BS_FLOATS) * 4;  // 65536
    cudaFuncSetAttribute(gemm_tf32_nt,
                         cudaFuncAttributeMaxDynamicSharedMemorySize, GEMM_SMEM);
    cudaFuncSetAttribute(flash_attn_kernel,
                         cudaFuncAttributeMaxDynamicSharedMemorySize, 114688);

    // Projections (tf32 tensor cores)
    gemm_tf32_nt<<<dim3(HIDDEN / 128, S_LEN / 128), 256, GEMM_SMEM>>>(x, Wq, q, S_LEN, HIDDEN, HIDDEN);
    gemm_tf32_nt<<<dim3(KVDIM / 128,  S_LEN / 128), 256, GEMM_SMEM>>>(x, Wk, k, S_LEN, KVDIM, HIDDEN);
    gemm_tf32_nt<<<dim3(KVDIM / 128,  S_LEN / 128), 256, GEMM_SMEM>>>(x, Wv, v, S_LEN, KVDIM, HIDDEN);

    // RoPE
    rope_tables_kernel<<<S_LEN, 64>>>(pos);
    rope_apply_kernel<<<dim3(S_LEN, HQ + HK), 64>>>();

    // Flash attention (fp32 CUDA cores — next optimization target)
    flash_attn_kernel<<<dim3(S_LEN / 64, HQ), 256, 114688>>>();

    // Output projection
    gemm_tf32_nt<<<dim3(HIDDEN / 128, S_LEN / 128), 256, GEMM_SMEM>>>(attn, Wo, out, S_LEN, HIDDEN, HIDDEN);
}

// round 4
// speedup vs baseline: 2.1148x; 1.6681x over previous
#include <cuda_runtime.h>
#include <cuda_bf16.h>
#include <math.h>

// Problem constants
#define S_LEN   3072
#define HIDDEN  2048
#define HQ      16
#define HK      2
#define HEADDIM 128
#define KVDIM   (HK * HEADDIM)   // 256

// ---------------------------------------------------------------------------
// Scratch (static device globals; no allocation allowed)
// ---------------------------------------------------------------------------
__device__ float g_Q[S_LEN * HIDDEN];      // [S, 16*128]
__device__ float g_K[S_LEN * KVDIM];       // [S, 2*128]
__device__ float g_V[S_LEN * KVDIM];
__device__ float g_attn[S_LEN * HIDDEN];   // attention output, pre-Wo
__device__ float g_cos[S_LEN * 64];
__device__ float g_sin[S_LEN * 64];

__device__ __forceinline__ unsigned f2tf32(float f) {
    unsigned r;
    asm("cvt.rna.tf32.f32 %0, %1;" : "=r"(r) : "f"(f));
    return r;
}

#define MMA_TF32(d, a0, a1, a2, a3, b0, b1)                                   \
    asm volatile(                                                             \
        "mma.sync.aligned.m16n8k8.row.col.f32.tf32.tf32.f32 "                 \
        "{%0,%1,%2,%3},{%4,%5,%6,%7},{%8,%9},{%0,%1,%2,%3};"                  \
        : "+f"(d[0]), "+f"(d[1]), "+f"(d[2]), "+f"(d[3])                      \
        : "r"(a0), "r"(a1), "r"(a2), "r"(a3), "r"(b0), "r"(b1))

// ---------------------------------------------------------------------------
// RoPE
// ---------------------------------------------------------------------------
__global__ void rope_tables_kernel(const int* __restrict__ pos_ids) {
    int s = blockIdx.x;
    int i = threadIdx.x;  // 0..63
    int pos = pos_ids[s];
    float invf = 1.0f / powf(10000.0f, (float)(2 * i) / 128.0f);
    double ang = (double)pos * (double)invf;
    double sv, cv;
    sincos(ang, &sv, &cv);
    g_cos[s * 64 + i] = (float)cv;
    g_sin[s * 64 + i] = (float)sv;
}

__global__ void rope_apply_kernel() {
    int s = blockIdx.x;
    int h = blockIdx.y;   // 0..17
    int i = threadIdx.x;  // 0..63
    float c  = g_cos[s * 64 + i];
    float sn = g_sin[s * 64 + i];
    float* base;
    if (h < HQ) base = g_Q + (size_t)s * HIDDEN + (size_t)h * HEADDIM;
    else        base = g_K + (size_t)s * KVDIM  + (size_t)(h - HQ) * HEADDIM;
    float x1 = base[i];
    float x2 = base[i + 64];
    base[i]      = x1 * c - x2 * sn;
    base[i + 64] = x2 * c + x1 * sn;
}

// ---------------------------------------------------------------------------
// TF32 tensor-core GEMM: C[M,N] = A[M,K]*B[N,K]^T.
// B2/C2 non-null => blockIdx.z==1 computes the second (B2,C2) problem
// (used to fuse the K and V projections into one launch).
// ---------------------------------------------------------------------------
#define MMA_TF32V(d, a, b)                                                    \
    asm volatile(                                                             \
        "mma.sync.aligned.m16n8k8.row.col.f32.tf32.tf32.f32 "                 \
        "{%0,%1,%2,%3},{%4,%5,%6,%7},{%8,%9},{%0,%1,%2,%3};"                  \
        : "+f"(d[0]), "+f"(d[1]), "+f"(d[2]), "+f"(d[3])                      \
        : "r"(a.x), "r"(a.y), "r"(a.z), "r"(a.w), "r"(b.x), "r"(b.y))

#define AS_FLOATS 4096
#define BS_FLOATS 4096

__global__ void __launch_bounds__(256) gemm_tf32_nt(
    const float* __restrict__ A, const float* __restrict__ B,
    float* __restrict__ C, int M, int N, int K,
    const float* __restrict__ B2, float* __restrict__ C2)
{
    extern __shared__ float sm[];
    float* Asm[2] = { sm,                 sm + AS_FLOATS };
    float* Bsm[2] = { sm + 2 * AS_FLOATS, sm + 2 * AS_FLOATS + BS_FLOATS };

    if (blockIdx.z == 1) { B = B2; C = C2; }

    const int tid  = threadIdx.x;
    const int lane = tid & 31;
    const int wid  = tid >> 5;
    const int warp_m = wid >> 2;
    const int warp_n = wid & 3;
    const int bm = blockIdx.y * 128;
    const int bn = blockIdx.x * 128;

    const float* Ab = A + (size_t)bm * K;
    const float* Bb = B + (size_t)bn * K;

    float acc[16][4];
#pragma unroll
    for (int i = 0; i < 16; i++)
#pragma unroll
        for (int j = 0; j < 4; j++) acc[i][j] = 0.0f;

    const int T = K >> 5;

    auto store_tile = [&](float* As, float* Bs, const float4* ra, const float4* rb) {
#pragma unroll
        for (int j = 0; j < 4; j++) {
            int i = tid + j * 256;
            int row = i >> 3;
            int kg  = (i & 7) << 2;
            int mtile = row >> 4, kstep = kg >> 3;
            int lane_s = (row & 7) << 2;
            int reg = ((row >> 3) & 1) | (((kg >> 2) & 1) << 1);
            float* pa = As + ((mtile * 4 + kstep) << 7) + reg;
            pa[(lane_s + 0) * 4] = __uint_as_float(f2tf32(ra[j].x));
            pa[(lane_s + 1) * 4] = __uint_as_float(f2tf32(ra[j].y));
            pa[(lane_s + 2) * 4] = __uint_as_float(f2tf32(ra[j].z));
            pa[(lane_s + 3) * 4] = __uint_as_float(f2tf32(ra[j].w));

            int ntile = row >> 3;
            int lane_b = (row & 7) << 2;
            int regb = (kg >> 2) & 1;
            float* pb = Bs + ((ntile * 4 + kstep) << 6) + regb;
            pb[(lane_b + 0) * 2] = __uint_as_float(f2tf32(rb[j].x));
            pb[(lane_b + 1) * 2] = __uint_as_float(f2tf32(rb[j].y));
            pb[(lane_b + 2) * 2] = __uint_as_float(f2tf32(rb[j].z));
            pb[(lane_b + 3) * 2] = __uint_as_float(f2tf32(rb[j].w));
        }
    };
    auto load_regs = [&](int t, float4* ra, float4* rb) {
        int k0 = t << 5;
#pragma unroll
        for (int j = 0; j < 4; j++) {
            int i = tid + j * 256;
            int row = i >> 3;
            int kg  = (i & 7) << 2;
            ra[j] = *(const float4*)&Ab[(size_t)row * K + k0 + kg];
            rb[j] = *(const float4*)&Bb[(size_t)row * K + k0 + kg];
        }
    };

    {
        float4 ra[4], rb[4];
        load_regs(0, ra, rb);
        store_tile(Asm[0], Bsm[0], ra, rb);
    }
    __syncthreads();

    for (int t = 0; t < T; t++) {
        const int buf = t & 1;
        float4 ra[4], rb[4];
        if (t + 1 < T) load_regs(t + 1, ra, rb);

        const float* As = Asm[buf];
        const float* Bs = Bsm[buf];
#pragma unroll
        for (int kstep = 0; kstep < 4; kstep++) {
            uint4 af[4];
            uint2 bf[4];
#pragma unroll
            for (int mi = 0; mi < 4; mi++)
                af[mi] = *(const uint4*)&As[(((warp_m * 4 + mi) * 4 + kstep) << 7) + lane * 4];
#pragma unroll
            for (int ni = 0; ni < 4; ni++)
                bf[ni] = *(const uint2*)&Bs[(((warp_n * 4 + ni) * 4 + kstep) << 6) + lane * 2];
#pragma unroll
            for (int mi = 0; mi < 4; mi++)
#pragma unroll
                for (int ni = 0; ni < 4; ni++)
                    MMA_TF32V(acc[mi * 4 + ni], af[mi], bf[ni]);
        }

        if (t + 1 < T) store_tile(Asm[1 - buf], Bsm[1 - buf], ra, rb);
        __syncthreads();
    }

#pragma unroll
    for (int mi = 0; mi < 4; mi++) {
#pragma unroll
        for (int ni = 0; ni < 4; ni++) {
            const float* d = acc[mi * 4 + ni];
            int r0 = bm + warp_m * 64 + mi * 16 + (lane >> 2);
            int c0 = bn + warp_n * 32 + ni * 8 + (lane & 3) * 2;
            *(float2*)&C[(size_t)r0 * N + c0]       = make_float2(d[0], d[1]);
            *(float2*)&C[(size_t)(r0 + 8) * N + c0] = make_float2(d[2], d[3]);
        }
    }
}

// ---------------------------------------------------------------------------
// Tensor-core flash attention (tf32, causal).
// Grid: (24 q-tiles, 16 heads), 256 threads. BM=128 (16 rows/warp), BN=64.
// Smem: Qraw[128][136] | Kst[64][136] | Vt[128][72] | Ps[8][16][68] = 176128 B
// ---------------------------------------------------------------------------
#define FA_SMEM_BYTES 176128

__global__ void __launch_bounds__(256) flash_attn_tc() {
    extern __shared__ float sm[];
    float* Qraw = sm;            // [128][136] tf32, scale folded
    float* Kst  = sm + 17408;    // [64][136]  tf32
    float* Vt   = sm + 26112;    // [128][72]  tf32, transposed [d][s]
    float* Ps   = sm + 35328;    // [8][16][68] per-warp P staging

    const int qt  = 23 - (int)blockIdx.x;   // heavy tiles first
    const int h   = blockIdx.y;
    const int kvh = h & (HK - 1);
    const int tid  = threadIdx.x;
    const int lane = tid & 31;
    const int wid  = tid >> 5;
    const int g = lane >> 2;     // groupID 0..7
    const int t = lane & 3;      // threadID_in_group
    const int qrow0 = qt * 128 + wid * 16;

    const float scale = 0.08838834764831845f;  // 1/sqrt(128)

    // Load Q tile (scale folded, tf32)
    {
        const float* Qg = g_Q + (size_t)(qt * 128) * HIDDEN + (size_t)h * HEADDIM;
#pragma unroll
        for (int j = 0; j < 16; j++) {
            int idx = tid + j * 256;
            int row = idx >> 5, c4 = (idx & 31) << 2;
            float4 v = *(const float4*)&Qg[(size_t)row * HIDDEN + c4];
            v.x = __uint_as_float(f2tf32(v.x * scale));
            v.y = __uint_as_float(f2tf32(v.y * scale));
            v.z = __uint_as_float(f2tf32(v.z * scale));
            v.w = __uint_as_float(f2tf32(v.w * scale));
            *(float4*)&Qraw[row * 136 + c4] = v;
        }
    }

    float m0 = -INFINITY, m1 = -INFINITY, l0 = 0.0f, l1 = 0.0f;
    float o[16][4];
#pragma unroll
    for (int dn = 0; dn < 16; dn++)
#pragma unroll
        for (int j = 0; j < 4; j++) o[dn][j] = 0.0f;

    const int nkt = 2 * qt + 2;
    for (int kt = 0; kt < nkt; kt++) {
        __syncthreads();   // protect prev-iter smem reads (also orders Q store)
        // K tile -> Kst raw [n][136]
        {
            const float* Kg = g_K + (size_t)(kt * 64) * KVDIM + (size_t)kvh * HEADDIM;
#pragma unroll
            for (int j = 0; j < 8; j++) {
                int idx = tid + j * 256;
                int n = idx >> 5, c4 = (idx & 31) << 2;
                float4 v = *(const float4*)&Kg[(size_t)n * KVDIM + c4];
                v.x = __uint_as_float(f2tf32(v.x));
                v.y = __uint_as_float(f2tf32(v.y));
                v.z = __uint_as_float(f2tf32(v.z));
                v.w = __uint_as_float(f2tf32(v.w));
                *(float4*)&Kst[n * 136 + c4] = v;
            }
        }
        // V tile -> Vt transposed [d][72]
        {
            const float* Vg = g_V + (size_t)(kt * 64) * KVDIM + (size_t)kvh * HEADDIM;
#pragma unroll
            for (int j = 0; j < 8; j++) {
                int idx = tid + j * 256;
                int s = idx & 63, d0 = (idx >> 6) << 2;
                float4 v = *(const float4*)&Vg[(size_t)s * KVDIM + d0];
                Vt[(d0 + 0) * 72 + s] = __uint_as_float(f2tf32(v.x));
                Vt[(d0 + 1) * 72 + s] = __uint_as_float(f2tf32(v.y));
                Vt[(d0 + 2) * 72 + s] = __uint_as_float(f2tf32(v.z));
                Vt[(d0 + 3) * 72 + s] = __uint_as_float(f2tf32(v.w));
            }
        }
        __syncthreads();

        // S = Q * K^T : 8 n-tiles of m16n8, K-loop 16 x k8
        float sa[8][4];
#pragma unroll
        for (int nt = 0; nt < 8; nt++)
#pragma unroll
            for (int j = 0; j < 4; j++) sa[nt][j] = 0.0f;

#pragma unroll
        for (int ks = 0; ks < 16; ks++) {
            int qa = (wid * 16 + g) * 136 + ks * 8 + t;
            unsigned a0 = __float_as_uint(Qraw[qa]);
            unsigned a1 = __float_as_uint(Qraw[qa + 8 * 136]);
            unsigned a2 = __float_as_uint(Qraw[qa + 4]);
            unsigned a3 = __float_as_uint(Qraw[qa + 8 * 136 + 4]);
#pragma unroll
            for (int nt = 0; nt < 8; nt++) {
                int kb = (nt * 8 + g) * 136 + ks * 8 + t;
                unsigned b0 = __float_as_uint(Kst[kb]);
                unsigned b1 = __float_as_uint(Kst[kb + 4]);
                MMA_TF32(sa[nt], a0, a1, a2, a3, b0, b1);
            }
        }

        // causal mask (scale already folded into Q)
        if (kt * 64 + 63 > qrow0) {
            int r0 = qrow0 + g, r1 = r0 + 8;
#pragma unroll
            for (int nt = 0; nt < 8; nt++) {
                int c = kt * 64 + nt * 8 + 2 * t;
                if (c     > r0) sa[nt][0] = -1e30f;
                if (c + 1 > r0) sa[nt][1] = -1e30f;
                if (c     > r1) sa[nt][2] = -1e30f;
                if (c + 1 > r1) sa[nt][3] = -1e30f;
            }
        }

        // online softmax
        float x0 = -1e30f, x1 = -1e30f;
#pragma unroll
        for (int nt = 0; nt < 8; nt++) {
            x0 = fmaxf(x0, fmaxf(sa[nt][0], sa[nt][1]));
            x1 = fmaxf(x1, fmaxf(sa[nt][2], sa[nt][3]));
        }
        x0 = fmaxf(x0, __shfl_xor_sync(0xffffffffu, x0, 1));
        x0 = fmaxf(x0, __shfl_xor_sync(0xffffffffu, x0, 2));
        x1 = fmaxf(x1, __shfl_xor_sync(0xffffffffu, x1, 1));
        x1 = fmaxf(x1, __shfl_xor_sync(0xffffffffu, x1, 2));
        float mn0 = fmaxf(m0, x0), mn1 = fmaxf(m1, x1);
        float al0 = __expf(m0 - mn0), al1 = __expf(m1 - mn1);
        m0 = mn0; m1 = mn1;

        float rs0 = 0.0f, rs1 = 0.0f;
        int pbase = wid * 1088 + g * 68 + 2 * t;
#pragma unroll
        for (int nt = 0; nt < 8; nt++) {
            float p0 = __expf(sa[nt][0] - mn0);
            float p1 = __expf(sa[nt][1] - mn0);
            float p2 = __expf(sa[nt][2] - mn1);
            float p3 = __expf(sa[nt][3] - mn1);
            rs0 += p0 + p1;
            rs1 += p2 + p3;
            *(float2*)&Ps[pbase + nt * 8] = make_float2(
                __uint_as_float(f2tf32(p0)), __uint_as_float(f2tf32(p1)));
            *(float2*)&Ps[pbase + 8 * 68 + nt * 8] = make_float2(
                __uint_as_float(f2tf32(p2)), __uint_as_float(f2tf32(p3)));
        }
        rs0 += __shfl_xor_sync(0xffffffffu, rs0, 1);
        rs0 += __shfl_xor_sync(0xffffffffu, rs0, 2);
        rs1 += __shfl_xor_sync(0xffffffffu, rs1, 1);
        rs1 += __shfl_xor_sync(0xffffffffu, rs1, 2);
        l0 = l0 * al0 + rs0;
        l1 = l1 * al1 + rs1;

#pragma unroll
        for (int dn = 0; dn < 16; dn++) {
            o[dn][0] *= al0; o[dn][1] *= al0;
            o[dn][2] *= al1; o[dn][3] *= al1;
        }
        __syncwarp();   // order Ps writes before fragment reads

        // O += P * V : 16 d-tiles, K-loop 8 x k8 (A frags from per-warp Ps)
#pragma unroll
        for (int kc = 0; kc < 8; kc++) {
            int pa = wid * 1088 + g * 68 + kc * 8 + t;
            unsigned a0 = __float_as_uint(Ps[pa]);
            unsigned a1 = __float_as_uint(Ps[pa + 8 * 68]);
            unsigned a2 = __float_as_uint(Ps[pa + 4]);
            unsigned a3 = __float_as_uint(Ps[pa + 8 * 68 + 4]);
#pragma unroll
            for (int dn = 0; dn < 16; dn++) {
                int vb = (dn * 8 + g) * 72 + kc * 8 + t;
                unsigned b0 = __float_as_uint(Vt[vb]);
                unsigned b1 = __float_as_uint(Vt[vb + 4]);
                MMA_TF32(o[dn], a0, a1, a2, a3, b0, b1);
            }
        }
        __syncwarp();   // Ps reads done before next-iter writes
    }

    // epilogue: normalize + store
    float inv0 = 1.0f / l0, inv1 = 1.0f / l1;
    int r0 = qrow0 + g, r1 = r0 + 8;
    float* O0 = g_attn + (size_t)r0 * HIDDEN + (size_t)h * HEADDIM;
    float* O1 = g_attn + (size_t)r1 * HIDDEN + (size_t)h * HEADDIM;
#pragma unroll
    for (int dn = 0; dn < 16; dn++) {
        *(float2*)&O0[dn * 8 + 2 * t] = make_float2(o[dn][0] * inv0, o[dn][1] * inv0);
        *(float2*)&O1[dn * 8 + 2 * t] = make_float2(o[dn][2] * inv1, o[dn][3] * inv1);
    }
}

// ---------------------------------------------------------------------------
// Launch
// ---------------------------------------------------------------------------
extern "C" void kernel_launch(void* const* d_in, const int* in_sizes, int n_in,
                              void* d_out, int out_size) {
    const float* x   = (const float*)d_in[0];
    const int*   pos = (const int*)d_in[2];
    const float* Wq  = (const float*)d_in[3];
    const float* Wk  = (const float*)d_in[4];
    const float* Wv  = (const float*)d_in[5];
    const float* Wo  = (const float*)d_in[6];
    float* out = (float*)d_out;

    float *q, *k, *v, *attn;
    cudaGetSymbolAddress((void**)&q,    g_Q);
    cudaGetSymbolAddress((void**)&k,    g_K);
    cudaGetSymbolAddress((void**)&v,    g_V);
    cudaGetSymbolAddress((void**)&attn, g_attn);

    const int GEMM_SMEM = 2 * (AS_FLOATS + BS_FLOATS) * 4;  // 65536
    cudaFuncSetAttribute(gemm_tf32_nt,
                         cudaFuncAttributeMaxDynamicSharedMemorySize, GEMM_SMEM);
    cudaFuncSetAttribute(flash_attn_tc,
                         cudaFuncAttributeMaxDynamicSharedMemorySize, FA_SMEM_BYTES);

    // Q projection
    gemm_tf32_nt<<<dim3(HIDDEN / 128, S_LEN / 128, 1), 256, GEMM_SMEM>>>(
        x, Wq, q, S_LEN, HIDDEN, HIDDEN, nullptr, nullptr);
    // K and V projections fused into one launch (z=0 -> K, z=1 -> V)
    gemm_tf32_nt<<<dim3(KVDIM / 128, S_LEN / 128, 2), 256, GEMM_SMEM>>>(
        x, Wk, k, S_LEN, KVDIM, HIDDEN, Wv, v);

    rope_tables_kernel<<<S_LEN, 64>>>(pos);
    rope_apply_kernel<<<dim3(S_LEN, HQ + HK), 64>>>();

    flash_attn_tc<<<dim3(S_LEN / 128, HQ), 256, FA_SMEM_BYTES>>>();

    gemm_tf32_nt<<<dim3(HIDDEN / 128, S_LEN / 128, 1), 256, GEMM_SMEM>>>(
        attn, Wo, out, S_LEN, HIDDEN, HIDDEN, nullptr, nullptr);
}